// round 1
// baseline (speedup 1.0000x reference)
#include <cuda_runtime.h>

// ---------------------------------------------------------------------------
// AttentionHead: O = softmax(causal(Q K^T * d^-0.5)) V,  Q/K/V = x @ W^T
// B=8, S=4096, D=1024, DK=64.  fp32 baseline (round 0).
// Phase 1: QKV projection GEMM (scale*log2e folded into Q).
// Phase 2: flash attention with base-2 online softmax, causal-balanced blocks.
// ---------------------------------------------------------------------------

constexpr int B  = 8;
constexpr int S  = 4096;
constexpr int D  = 1024;
constexpr int DK = 64;
constexpr int M  = B * S;           // 32768 rows

// scratch (device globals: allocation-free per harness rules)
__device__ float g_Q[M * DK];
__device__ float g_K[M * DK];
__device__ float g_V[M * DK];

__device__ __forceinline__ float ex2f(float x) {
    float y;
    asm("ex2.approx.ftz.f32 %0, %1;" : "=f"(y) : "f"(x));
    return y;
}

// ---------------------------------------------------------------------------
// Phase 1: C[M,64] = X[M,1024] @ W^T,  W is [64,1024] row-major.
// Block tile 256(M) x 64(N), BK=16, 256 threads, 8x8 micro-tiles.
// blockIdx.y selects {Q,K,V}; Q additionally scaled by d^-0.5 * log2(e).
// ---------------------------------------------------------------------------
__global__ __launch_bounds__(256, 2)
void qkv_proj_kernel(const float* __restrict__ x,
                     const float* __restrict__ wq,
                     const float* __restrict__ wk,
                     const float* __restrict__ wv)
{
    __shared__ float Xs[16 * 260];   // X^T tile [k][m], stride 260
    __shared__ float Ws[16 * 68];    // W^T tile [k][n], stride 68

    const int z = blockIdx.y;
    const float* __restrict__ w = (z == 0) ? wq : (z == 1) ? wk : wv;
    float* __restrict__ outp     = (z == 0) ? g_Q : (z == 1) ? g_K : g_V;

    const int m0  = blockIdx.x * 256;
    const int tid = threadIdx.x;
    const int tym = tid >> 3;   // 0..31 -> 8 M-rows each
    const int txn = tid & 7;    // 0..7  -> 8 N-cols each

    float acc[8][8];
#pragma unroll
    for (int i = 0; i < 8; i++)
#pragma unroll
        for (int j = 0; j < 8; j++) acc[i][j] = 0.0f;

    const float4* x4 = (const float4*)x;
    const float4* w4 = (const float4*)w;

    const int nld = tid >> 2;   // 0..63 (W row)
    const int kqw = tid & 3;

    for (int k0 = 0; k0 < D; k0 += 16) {
        __syncthreads();
        // X tile 256x16 -> transposed into smem
#pragma unroll
        for (int p = 0; p < 4; p++) {
            int i4 = tid + p * 256;
            int mm = i4 >> 2;
            int kq = i4 & 3;
            float4 v = x4[(m0 + mm) * (D / 4) + (k0 >> 2) + kq];
            Xs[(4 * kq + 0) * 260 + mm] = v.x;
            Xs[(4 * kq + 1) * 260 + mm] = v.y;
            Xs[(4 * kq + 2) * 260 + mm] = v.z;
            Xs[(4 * kq + 3) * 260 + mm] = v.w;
        }
        // W tile 64x16 -> transposed into smem
        {
            float4 v = w4[nld * (D / 4) + (k0 >> 2) + kqw];
            Ws[(4 * kqw + 0) * 68 + nld] = v.x;
            Ws[(4 * kqw + 1) * 68 + nld] = v.y;
            Ws[(4 * kqw + 2) * 68 + nld] = v.z;
            Ws[(4 * kqw + 3) * 68 + nld] = v.w;
        }
        __syncthreads();
#pragma unroll
        for (int k = 0; k < 16; k++) {
            float4 a0 = *(const float4*)&Xs[k * 260 + 8 * tym];
            float4 a1 = *(const float4*)&Xs[k * 260 + 8 * tym + 4];
            float4 b0 = *(const float4*)&Ws[k * 68 + 8 * txn];
            float4 b1 = *(const float4*)&Ws[k * 68 + 8 * txn + 4];
            float ra[8] = {a0.x, a0.y, a0.z, a0.w, a1.x, a1.y, a1.z, a1.w};
            float rb[8] = {b0.x, b0.y, b0.z, b0.w, b1.x, b1.y, b1.z, b1.w};
#pragma unroll
            for (int i = 0; i < 8; i++)
#pragma unroll
                for (int j = 0; j < 8; j++)
                    acc[i][j] = fmaf(ra[i], rb[j], acc[i][j]);
        }
    }

    // scale*log2(e) folded into Q so attention exp uses ex2 directly
    const float sc = (z == 0) ? (float)(1.4426950408889634 / 32.0) : 1.0f;
    float4* o4 = (float4*)outp;
#pragma unroll
    for (int i = 0; i < 8; i++) {
        int row = m0 + 8 * tym + i;
        o4[row * (DK / 4) + 2 * txn] =
            make_float4(acc[i][0] * sc, acc[i][1] * sc, acc[i][2] * sc, acc[i][3] * sc);
        o4[row * (DK / 4) + 2 * txn + 1] =
            make_float4(acc[i][4] * sc, acc[i][5] * sc, acc[i][6] * sc, acc[i][7] * sc);
    }
}

// ---------------------------------------------------------------------------
// Phase 2: flash attention, fp32, base-2 online softmax.
// Block = 256 threads, processes TWO q-tiles (j and 31-j) of 128 rows each
// for one batch -> uniform 33 key-tile iterations per block, 128 blocks total.
// smem: Q^T[64][132], K^T[64][132], V[128][68], P[128][132]  (~166 KB dynamic)
// ---------------------------------------------------------------------------
constexpr int SM_QT = 64 * 132;
constexpr int SM_KT = 64 * 132;
constexpr int SM_V  = 128 * 68;
constexpr int SM_P  = 128 * 132;
constexpr int SMEM_BYTES = (SM_QT + SM_KT + SM_V + SM_P) * 4;  // 169984

__global__ __launch_bounds__(256, 1)
void attn_kernel(float* __restrict__ out)
{
    extern __shared__ float sm[];
    float* QT = sm;
    float* KT = QT + SM_QT;
    float* Vt = KT + SM_KT;
    float* Ps = Vt + SM_V;

    const int b   = blockIdx.y;
    const int pj  = blockIdx.x;      // 0..15 -> q-tiles pj and 31-pj
    const int tid = threadIdx.x;
    const int ty  = tid >> 4;        // 0..15 -> 8 q-rows each
    const int tx  = tid & 15;        // 0..15 -> 8 key-cols (split 4+4), 4 dk-cols

    const float4* gQ4 = (const float4*)g_Q;
    const float4* gK4 = (const float4*)g_K;
    const float4* gV4 = (const float4*)g_V;
    float4* out4 = (float4*)out;

    const float NEG_INF = __int_as_float(0xff800000);

    for (int qsel = 0; qsel < 2; qsel++) {
        const int qt = qsel ? (31 - pj) : pj;
        const int q0 = qt * 128;

        __syncthreads();
        // load Q^T (already scaled by d^-0.5 * log2e)
#pragma unroll
        for (int p = 0; p < 8; p++) {
            int i4 = tid + p * 256;
            int q  = i4 >> 4;
            int kq = i4 & 15;
            float4 v = gQ4[(b * S + q0 + q) * 16 + kq];
            QT[(4 * kq + 0) * 132 + q] = v.x;
            QT[(4 * kq + 1) * 132 + q] = v.y;
            QT[(4 * kq + 2) * 132 + q] = v.z;
            QT[(4 * kq + 3) * 132 + q] = v.w;
        }

        float o[8][4];
        float m[8], l[8];
#pragma unroll
        for (int i = 0; i < 8; i++) {
            m[i] = NEG_INF;
            l[i] = 0.0f;
#pragma unroll
            for (int j = 0; j < 4; j++) o[i][j] = 0.0f;
        }

        for (int kt = 0; kt <= qt; kt++) {
            const int t0 = kt * 128;
            __syncthreads();   // previous PV / QT-load complete
            // load K^T and V tiles
#pragma unroll
            for (int p = 0; p < 8; p++) {
                int i4 = tid + p * 256;
                int t  = i4 >> 4;
                int kq = i4 & 15;
                float4 v = gK4[(b * S + t0 + t) * 16 + kq];
                KT[(4 * kq + 0) * 132 + t] = v.x;
                KT[(4 * kq + 1) * 132 + t] = v.y;
                KT[(4 * kq + 2) * 132 + t] = v.z;
                KT[(4 * kq + 3) * 132 + t] = v.w;
                float4 vv = gV4[(b * S + t0 + t) * 16 + kq];
                *(float4*)&Vt[t * 68 + 4 * kq] = vv;
            }
            __syncthreads();

            // S = Q K^T  (128x128 tile, 8x8 per thread)
            float sv[8][8];
#pragma unroll
            for (int i = 0; i < 8; i++)
#pragma unroll
                for (int j = 0; j < 8; j++) sv[i][j] = 0.0f;

#pragma unroll 8
            for (int k = 0; k < 64; k++) {
                float4 a0 = *(const float4*)&QT[k * 132 + 8 * ty];
                float4 a1 = *(const float4*)&QT[k * 132 + 8 * ty + 4];
                float4 b0 = *(const float4*)&KT[k * 132 + 4 * tx];
                float4 b1 = *(const float4*)&KT[k * 132 + 64 + 4 * tx];
                float ra[8] = {a0.x, a0.y, a0.z, a0.w, a1.x, a1.y, a1.z, a1.w};
                float rb[8] = {b0.x, b0.y, b0.z, b0.w, b1.x, b1.y, b1.z, b1.w};
#pragma unroll
                for (int i = 0; i < 8; i++)
#pragma unroll
                    for (int j = 0; j < 8; j++)
                        sv[i][j] = fmaf(ra[i], rb[j], sv[i][j]);
            }

            // causal mask (diagonal tile only)
            if (kt == qt) {
#pragma unroll
                for (int i = 0; i < 8; i++) {
                    int qi = 8 * ty + i;
#pragma unroll
                    for (int j = 0; j < 8; j++) {
                        int tj = (j < 4) ? (4 * tx + j) : (60 + 4 * tx + j);
                        if (tj > qi) sv[i][j] = NEG_INF;
                    }
                }
            }

            // online softmax (base-2), P written to smem
#pragma unroll
            for (int i = 0; i < 8; i++) {
                float mt = sv[i][0];
#pragma unroll
                for (int j = 1; j < 8; j++) mt = fmaxf(mt, sv[i][j]);
#pragma unroll
                for (int off = 8; off >= 1; off >>= 1)
                    mt = fmaxf(mt, __shfl_xor_sync(0xffffffffu, mt, off));
                float mn    = fmaxf(m[i], mt);
                float alpha = ex2f(m[i] - mn);
                float pv[8];
                float rs = 0.0f;
#pragma unroll
                for (int j = 0; j < 8; j++) { pv[j] = ex2f(sv[i][j] - mn); rs += pv[j]; }
#pragma unroll
                for (int off = 8; off >= 1; off >>= 1)
                    rs += __shfl_xor_sync(0xffffffffu, rs, off);
                l[i] = l[i] * alpha + rs;
                m[i] = mn;
#pragma unroll
                for (int j = 0; j < 4; j++) o[i][j] *= alpha;
                *(float4*)&Ps[(8 * ty + i) * 132 + 4 * tx] =
                    make_float4(pv[0], pv[1], pv[2], pv[3]);
                *(float4*)&Ps[(8 * ty + i) * 132 + 64 + 4 * tx] =
                    make_float4(pv[4], pv[5], pv[6], pv[7]);
            }
            __syncthreads();

            // O += P V   (thread: 8 q-rows x 4 dk-cols)
#pragma unroll 4
            for (int t = 0; t < 128; t++) {
                float4 rv = *(const float4*)&Vt[t * 68 + 4 * tx];
#pragma unroll
                for (int i = 0; i < 8; i++) {
                    float rp = Ps[(8 * ty + i) * 132 + t];
                    o[i][0] = fmaf(rp, rv.x, o[i][0]);
                    o[i][1] = fmaf(rp, rv.y, o[i][1]);
                    o[i][2] = fmaf(rp, rv.z, o[i][2]);
                    o[i][3] = fmaf(rp, rv.w, o[i][3]);
                }
            }
        }

        // epilogue: normalize and store
#pragma unroll
        for (int i = 0; i < 8; i++) {
            float inv = 1.0f / l[i];
            out4[(b * S + q0 + 8 * ty + i) * 16 + tx] =
                make_float4(o[i][0] * inv, o[i][1] * inv, o[i][2] * inv, o[i][3] * inv);
        }
    }
}

// ---------------------------------------------------------------------------
extern "C" void kernel_launch(void* const* d_in, const int* in_sizes, int n_in,
                              void* d_out, int out_size)
{
    const float* x  = (const float*)d_in[0];
    const float* wq = (const float*)d_in[1];
    const float* wk = (const float*)d_in[2];
    const float* wv = (const float*)d_in[3];
    float* out = (float*)d_out;

    cudaFuncSetAttribute(attn_kernel,
                         cudaFuncAttributeMaxDynamicSharedMemorySize, SMEM_BYTES);

    qkv_proj_kernel<<<dim3(M / 256, 3), 256>>>(x, wq, wk, wv);
    attn_kernel<<<dim3(16, B), 256, SMEM_BYTES>>>(out);
}

// round 4
// speedup vs baseline: 1.7493x; 1.7493x over previous
#include <cuda_runtime.h>
#include <cstdint>

// ---------------------------------------------------------------------------
// AttentionHead  B=8 S=4096 D=1024 DK=64
// Round 4: tf32 mma.sync with RNA rounding + selective 3-term compensation.
//   Q,K path (softmax-insensitive): single tf32 term.
//   V path + PV (directly visible in O): 3xTF32 split -> ~fp32 accuracy.
// ---------------------------------------------------------------------------

constexpr int B  = 8;
constexpr int S  = 4096;
constexpr int D  = 1024;
constexpr int DK = 64;
constexpr int M  = B * S;

__device__ float g_Q[M * DK];
__device__ float g_K[M * DK];
__device__ float g_V[M * DK];

__device__ __forceinline__ float ex2f(float x) {
    float y; asm("ex2.approx.ftz.f32 %0, %1;" : "=f"(y) : "f"(x)); return y;
}
__device__ __forceinline__ uint32_t tf32_rna(float f) {
    uint32_t u; asm("cvt.rna.tf32.f32 %0, %1;" : "=r"(u) : "f"(f)); return u;
}
// split f = hi + lo (both tf32-representable, RNA)
__device__ __forceinline__ void tf32_split(float f, uint32_t& hi, uint32_t& lo) {
    hi = tf32_rna(f);
    lo = tf32_rna(f - __uint_as_float(hi));
}
__device__ __forceinline__ void cpa16(void* dst_smem, const void* src) {
    uint32_t a;
    asm("{ .reg .u64 t; cvta.to.shared.u64 t, %1; cvt.u32.u64 %0, t; }"
        : "=r"(a) : "l"(dst_smem));
    asm volatile("cp.async.cg.shared.global [%0], [%1], 16;" :: "r"(a), "l"(src));
}
#define CPA_COMMIT() asm volatile("cp.async.commit_group;" ::: "memory")
template <int N>
__device__ __forceinline__ void cpa_wait() {
    asm volatile("cp.async.wait_group %0;" :: "n"(N) : "memory");
}

// m16n8k8 tf32 HMMA. A row-major frag, B col-major frag, f32 accum.
__device__ __forceinline__ void mma8(float c[4], const uint32_t a[4],
                                     uint32_t b0, uint32_t b1) {
    asm volatile(
        "mma.sync.aligned.m16n8k8.row.col.f32.tf32.tf32.f32 "
        "{%0,%1,%2,%3}, {%4,%5,%6,%7}, {%8,%9}, {%0,%1,%2,%3};"
        : "+f"(c[0]), "+f"(c[1]), "+f"(c[2]), "+f"(c[3])
        : "r"(a[0]), "r"(a[1]), "r"(a[2]), "r"(a[3]), "r"(b0), "r"(b1));
}

constexpr float NEG = -1e30f;

// ---------------------------------------------------------------------------
// Phase 1: C[M,192] = X[M,1024] @ [wQ|wK|wV]^T
// CTA 128x192, BK=32, 8 warps (4M x 2N, warp tile 32x96), 2-stage cp.async.
// Q,K cols: 1 tf32 term.  V cols (n>=128): 3 terms.
// ---------------------------------------------------------------------------
constexpr int PXS = 128 * 36;
constexpr int PWS = 192 * 36;
constexpr int PSTG = PXS + PWS;
constexpr int PROJ_SMEM = 2 * PSTG * 4;       // 92160 B

__global__ __launch_bounds__(256, 1)
void proj_kernel(const float* __restrict__ x,
                 const float* __restrict__ wq,
                 const float* __restrict__ wk,
                 const float* __restrict__ wv)
{
    extern __shared__ float ps[];
    const int tid  = threadIdx.x;
    const int lane = tid & 31;
    const int warp = tid >> 5;
    const int wm   = warp & 3;
    const int wn   = warp >> 2;
    const int m0   = blockIdx.x * 128;

    auto load_stage = [&](int st, int k0) {
        float* xs = ps + st * PSTG;
        float* ws = xs + PXS;
#pragma unroll
        for (int p = 0; p < 4; p++) {
            int c = tid + p * 256;
            int t = c >> 3, seg = c & 7;
            cpa16(xs + t * 36 + seg * 4, x + (size_t)(m0 + t) * D + k0 + seg * 4);
        }
#pragma unroll
        for (int p = 0; p < 6; p++) {
            int c = tid + p * 256;
            int n = c >> 3, seg = c & 7;
            const float* w = (n < 64) ? wq : (n < 128) ? wk : wv;
            cpa16(ws + n * 36 + seg * 4, w + (size_t)(n & 63) * D + k0 + seg * 4);
        }
        CPA_COMMIT();
    };

    float acc[2][12][4];
#pragma unroll
    for (int mt = 0; mt < 2; mt++)
#pragma unroll
        for (int nt = 0; nt < 12; nt++)
#pragma unroll
            for (int e = 0; e < 4; e++) acc[mt][nt][e] = 0.0f;

    load_stage(0, 0);

    for (int it = 0; it < 32; ++it) {
        if (it + 1 < 32) { load_stage((it + 1) & 1, (it + 1) * 32); cpa_wait<1>(); }
        else             { cpa_wait<0>(); }
        __syncthreads();

        const float* xs = ps + (it & 1) * PSTG;
        const float* ws = xs + PXS;
        const float* aB = xs + (wm * 32 + (lane >> 2)) * 36 + (lane & 3);
        const float* bB = ws + (wn * 96 + (lane >> 2)) * 36 + (lane & 3);

#pragma unroll
        for (int s = 0; s < 4; s++) {
            uint32_t ah[2][4], al[2][4];
#pragma unroll
            for (int mt = 0; mt < 2; mt++) {
                const float* ap = aB + mt * 16 * 36 + s * 8;
                tf32_split(ap[0],           ah[mt][0], al[mt][0]);
                tf32_split(ap[8 * 36],      ah[mt][1], al[mt][1]);
                tf32_split(ap[4],           ah[mt][2], al[mt][2]);
                tf32_split(ap[8 * 36 + 4],  ah[mt][3], al[mt][3]);
            }
#pragma unroll
            for (int nt = 0; nt < 12; nt++) {
                const float* bp = bB + nt * 8 * 36 + s * 8;
                const bool isv = (wn == 1) && (nt >= 4);   // V columns (n>=128)
                uint32_t bh0, bl0, bh1, bl1;
                tf32_split(bp[0], bh0, bl0);
                tf32_split(bp[4], bh1, bl1);
                mma8(acc[0][nt], ah[0], bh0, bh1);
                mma8(acc[1][nt], ah[1], bh0, bh1);
                if (isv) {
                    mma8(acc[0][nt], al[0], bh0, bh1);
                    mma8(acc[1][nt], al[1], bh0, bh1);
                    mma8(acc[0][nt], ah[0], bl0, bl1);
                    mma8(acc[1][nt], ah[1], bl0, bl1);
                }
            }
        }
        __syncthreads();
    }

    const float SC = (float)(1.4426950408889634 / 32.0);
#pragma unroll
    for (int mt = 0; mt < 2; mt++) {
#pragma unroll
        for (int nt = 0; nt < 12; nt++) {
            int col = wn * 96 + nt * 8 + 2 * (lane & 3);
            float* outp = (col < 64) ? g_Q : (col < 128) ? g_K : g_V;
            float sc = (col < 64) ? SC : 1.0f;
            int lc  = col & 63;
            int row = m0 + wm * 32 + mt * 16 + (lane >> 2);
            *(float2*)(outp + (size_t)row * DK + lc) =
                make_float2(acc[mt][nt][0] * sc, acc[mt][nt][1] * sc);
            *(float2*)(outp + (size_t)(row + 8) * DK + lc) =
                make_float2(acc[mt][nt][2] * sc, acc[mt][nt][3] * sc);
        }
    }
}

// ---------------------------------------------------------------------------
// Phase 2: flash attention.  QK^T: 1-term tf32 (rna).  PV: 3-term tf32.
// 8 warps x 16 q-rows, 128 kv-tile, causal-paired q-tiles (33 tiles/block).
// ---------------------------------------------------------------------------
constexpr int KSZ  = 128 * 68;
constexpr int VSZ  = 128 * 72;
constexpr int STG  = KSZ + VSZ;
constexpr int POFF = 2 * STG;
constexpr int ATTN_SMEM = (POFF + 128 * 132) * 4;  // 210944 B

__global__ __launch_bounds__(256, 1)
void attn_kernel(float* __restrict__ out)
{
    extern __shared__ float sm[];
    const int b    = blockIdx.y;
    const int pj   = blockIdx.x;
    const int tid  = threadIdx.x;
    const int lane = tid & 31;
    const int warp = tid >> 5;
    const int wb   = warp * 16;
    const int p4   = lane >> 2;
    const int q4   = lane & 3;

    float* Ps = sm + POFF;

    auto load_kv = [&](int kt, int st) {
        float* Ks = sm + st * STG;
        float* Vs = Ks + KSZ;
        const int t0 = kt * 128;
#pragma unroll
        for (int p = 0; p < 8; p++) {
            int c = tid + p * 256;
            int t = c >> 4, seg = c & 15;
            cpa16(Ks + t * 68 + seg * 4, g_K + ((size_t)(b * S + t0 + t)) * 64 + seg * 4);
        }
#pragma unroll
        for (int p = 0; p < 8; p++) {
            int c = tid + p * 256;
            int t = c >> 4, seg = c & 15;
            cpa16(Vs + t * 72 + seg * 4, g_V + ((size_t)(b * S + t0 + t)) * 64 + seg * 4);
        }
        CPA_COMMIT();
    };

    for (int qsel = 0; qsel < 2; qsel++) {
        const int qt = qsel ? (31 - pj) : pj;
        const int q0 = qt * 128;
        const int nt = qt + 1;

        load_kv(0, 0);

        // Q a-frags, rna-rounded once per q-tile
        uint32_t qa[8][4];
#pragma unroll
        for (int s = 0; s < 8; s++) {
            const float* qp = g_Q + ((size_t)(b * S + q0 + wb + p4)) * 64 + s * 8 + q4;
            qa[s][0] = tf32_rna(qp[0]);
            qa[s][1] = tf32_rna(qp[8 * 64]);
            qa[s][2] = tf32_rna(qp[4]);
            qa[s][3] = tf32_rna(qp[8 * 64 + 4]);
        }

        float of[8][4];
        float m0r = NEG, m1r = NEG, l0 = 0.0f, l1 = 0.0f;
#pragma unroll
        for (int j = 0; j < 8; j++)
#pragma unroll
            for (int e = 0; e < 4; e++) of[j][e] = 0.0f;

        for (int it = 0; it < nt; ++it) {
            const int st = it & 1;
            if (it + 1 < nt) { load_kv(it + 1, st ^ 1); cpa_wait<1>(); }
            else             { cpa_wait<0>(); }
            __syncthreads();

            const float* Ks = sm + st * STG;
            const float* Vs = Ks + KSZ;

            // ---- S = Q K^T ----
            float sf[16][4];
#pragma unroll
            for (int j = 0; j < 16; j++)
#pragma unroll
                for (int e = 0; e < 4; e++) sf[j][e] = 0.0f;

            const float* kB = Ks + p4 * 68 + q4;
#pragma unroll 4
            for (int j = 0; j < 16; j++) {
                const float* kp = kB + j * 8 * 68;
#pragma unroll
                for (int s = 0; s < 8; s++) {
                    uint32_t b0 = tf32_rna(kp[s * 8]);
                    uint32_t b1 = tf32_rna(kp[s * 8 + 4]);
                    mma8(sf[j], qa[s], b0, b1);
                }
            }

            // ---- causal mask on diagonal tile ----
            if (it == qt) {
                int r0 = wb + p4;
#pragma unroll
                for (int j = 0; j < 16; j++) {
                    int c0 = j * 8 + 2 * q4;
                    if (c0     > r0)     sf[j][0] = NEG;
                    if (c0 + 1 > r0)     sf[j][1] = NEG;
                    if (c0     > r0 + 8) sf[j][2] = NEG;
                    if (c0 + 1 > r0 + 8) sf[j][3] = NEG;
                }
            }

            // ---- online softmax (base 2) ----
            float mx0 = NEG, mx1 = NEG;
#pragma unroll
            for (int j = 0; j < 16; j++) {
                mx0 = fmaxf(mx0, fmaxf(sf[j][0], sf[j][1]));
                mx1 = fmaxf(mx1, fmaxf(sf[j][2], sf[j][3]));
            }
            mx0 = fmaxf(mx0, __shfl_xor_sync(0xffffffffu, mx0, 1));
            mx0 = fmaxf(mx0, __shfl_xor_sync(0xffffffffu, mx0, 2));
            mx1 = fmaxf(mx1, __shfl_xor_sync(0xffffffffu, mx1, 1));
            mx1 = fmaxf(mx1, __shfl_xor_sync(0xffffffffu, mx1, 2));
            float mn0 = fmaxf(m0r, mx0), mn1 = fmaxf(m1r, mx1);
            float al0 = ex2f(m0r - mn0), al1 = ex2f(m1r - mn1);
            m0r = mn0; m1r = mn1;

            float rs0 = 0.0f, rs1 = 0.0f;
            float* pw = Ps + (wb + p4) * 132 + 2 * q4;
#pragma unroll
            for (int j = 0; j < 16; j++) {
                float p00 = ex2f(sf[j][0] - mn0);
                float p01 = ex2f(sf[j][1] - mn0);
                float p10 = ex2f(sf[j][2] - mn1);
                float p11 = ex2f(sf[j][3] - mn1);
                rs0 += p00 + p01;
                rs1 += p10 + p11;
                *(float2*)(pw + j * 8)           = make_float2(p00, p01);
                *(float2*)(pw + 8 * 132 + j * 8) = make_float2(p10, p11);
            }
            rs0 += __shfl_xor_sync(0xffffffffu, rs0, 1);
            rs0 += __shfl_xor_sync(0xffffffffu, rs0, 2);
            rs1 += __shfl_xor_sync(0xffffffffu, rs1, 1);
            rs1 += __shfl_xor_sync(0xffffffffu, rs1, 2);
            l0 = l0 * al0 + rs0;
            l1 = l1 * al1 + rs1;
#pragma unroll
            for (int j = 0; j < 8; j++) {
                of[j][0] *= al0; of[j][1] *= al0;
                of[j][2] *= al1; of[j][3] *= al1;
            }
            __syncwarp();   // P rows wb..wb+15 are warp-private

            // ---- O += P V  (3-term tf32) ----
            const float* pA = Ps + (wb + p4) * 132 + q4;
            const float* vB = Vs + q4 * 72 + p4;
#pragma unroll 2
            for (int s2 = 0; s2 < 16; s2++) {
                uint32_t ph[4], pl[4];
                tf32_split(pA[s2 * 8],           ph[0], pl[0]);
                tf32_split(pA[8 * 132 + s2 * 8], ph[1], pl[1]);
                tf32_split(pA[s2 * 8 + 4],       ph[2], pl[2]);
                tf32_split(pA[8 * 132 + s2 * 8 + 4], ph[3], pl[3]);
                const float* vp = vB + s2 * 8 * 72;
#pragma unroll
                for (int j2 = 0; j2 < 8; j2++) {
                    uint32_t vh0, vl0, vh1, vl1;
                    tf32_split(vp[j2 * 8],          vh0, vl0);
                    tf32_split(vp[4 * 72 + j2 * 8], vh1, vl1);
                    mma8(of[j2], ph, vh0, vh1);
                    mma8(of[j2], pl, vh0, vh1);
                    mma8(of[j2], ph, vl0, vl1);
                }
            }
            __syncthreads();
        }

        // ---- epilogue ----
        float inv0 = 1.0f / l0, inv1 = 1.0f / l1;
        float* orow0 = out + ((size_t)(b * S + q0 + wb + p4)) * 64 + 2 * q4;
        float* orow1 = orow0 + 8 * 64;
#pragma unroll
        for (int j2 = 0; j2 < 8; j2++) {
            *(float2*)(orow0 + j2 * 8) = make_float2(of[j2][0] * inv0, of[j2][1] * inv0);
            *(float2*)(orow1 + j2 * 8) = make_float2(of[j2][2] * inv1, of[j2][3] * inv1);
        }
    }
}

// ---------------------------------------------------------------------------
extern "C" void kernel_launch(void* const* d_in, const int* in_sizes, int n_in,
                              void* d_out, int out_size)
{
    const float* x  = (const float*)d_in[0];
    const float* wq = (const float*)d_in[1];
    const float* wk = (const float*)d_in[2];
    const float* wv = (const float*)d_in[3];
    float* out = (float*)d_out;

    cudaFuncSetAttribute(proj_kernel,
                         cudaFuncAttributeMaxDynamicSharedMemorySize, PROJ_SMEM);
    cudaFuncSetAttribute(attn_kernel,
                         cudaFuncAttributeMaxDynamicSharedMemorySize, ATTN_SMEM);

    proj_kernel<<<M / 128, 256, PROJ_SMEM>>>(x, wq, wk, wv);
    attn_kernel<<<dim3(16, B), 256, ATTN_SMEM>>>(out);
}

// round 5
// speedup vs baseline: 2.9023x; 1.6591x over previous
#include <cuda_runtime.h>
#include <cstdint>

// ---------------------------------------------------------------------------
// AttentionHead  B=8 S=4096 D=1024 DK=64
// Round 5: all-1-term tf32 RNA. Q/K/V pre-rounded to tf32-exact fp32 in the
// projection epilogue; P rounded once at smem store. Attention inner loops
// are pure LDS + HMMA (no CVT). rel_err budget model: ~2.5e-4 < 1e-3.
// ---------------------------------------------------------------------------

constexpr int B  = 8;
constexpr int S  = 4096;
constexpr int D  = 1024;
constexpr int DK = 64;
constexpr int M  = B * S;

__device__ float g_Q[M * DK];
__device__ float g_K[M * DK];
__device__ float g_V[M * DK];

__device__ __forceinline__ float ex2f(float x) {
    float y; asm("ex2.approx.ftz.f32 %0, %1;" : "=f"(y) : "f"(x)); return y;
}
__device__ __forceinline__ uint32_t tf32_rna(float f) {
    uint32_t u; asm("cvt.rna.tf32.f32 %0, %1;" : "=r"(u) : "f"(f)); return u;
}
__device__ __forceinline__ uint32_t f2u(float f) { return __float_as_uint(f); }

__device__ __forceinline__ void cpa16(void* dst_smem, const void* src) {
    uint32_t a;
    asm("{ .reg .u64 t; cvta.to.shared.u64 t, %1; cvt.u32.u64 %0, t; }"
        : "=r"(a) : "l"(dst_smem));
    asm volatile("cp.async.cg.shared.global [%0], [%1], 16;" :: "r"(a), "l"(src));
}
#define CPA_COMMIT() asm volatile("cp.async.commit_group;" ::: "memory")
template <int N>
__device__ __forceinline__ void cpa_wait() {
    asm volatile("cp.async.wait_group %0;" :: "n"(N) : "memory");
}

// m16n8k8 tf32 HMMA. A row-major frag, B col-major frag, f32 accum.
__device__ __forceinline__ void mma8(float c[4], const uint32_t a[4],
                                     uint32_t b0, uint32_t b1) {
    asm volatile(
        "mma.sync.aligned.m16n8k8.row.col.f32.tf32.tf32.f32 "
        "{%0,%1,%2,%3}, {%4,%5,%6,%7}, {%8,%9}, {%0,%1,%2,%3};"
        : "+f"(c[0]), "+f"(c[1]), "+f"(c[2]), "+f"(c[3])
        : "r"(a[0]), "r"(a[1]), "r"(a[2]), "r"(a[3]), "r"(b0), "r"(b1));
}

constexpr float NEG = -1e30f;

// ---------------------------------------------------------------------------
// Phase 1: C[M,192] = X[M,1024] @ [wQ|wK|wV]^T   (1-term tf32 RNA)
// CTA 128x192, BK=32, 8 warps (4M x 2N, warp 32x96), 2-stage cp.async.
// Epilogue rounds outputs to tf32-exact fp32 (Q also scaled).
// ---------------------------------------------------------------------------
constexpr int PXS = 128 * 36;
constexpr int PWS = 192 * 36;
constexpr int PSTG = PXS + PWS;
constexpr int PROJ_SMEM = 2 * PSTG * 4;       // 92160 B

__global__ __launch_bounds__(256, 1)
void proj_kernel(const float* __restrict__ x,
                 const float* __restrict__ wq,
                 const float* __restrict__ wk,
                 const float* __restrict__ wv)
{
    extern __shared__ float ps[];
    const int tid  = threadIdx.x;
    const int lane = tid & 31;
    const int warp = tid >> 5;
    const int wm   = warp & 3;
    const int wn   = warp >> 2;
    const int m0   = blockIdx.x * 128;

    auto load_stage = [&](int st, int k0) {
        float* xs = ps + st * PSTG;
        float* ws = xs + PXS;
#pragma unroll
        for (int p = 0; p < 4; p++) {
            int c = tid + p * 256;
            int t = c >> 3, seg = c & 7;
            cpa16(xs + t * 36 + seg * 4, x + (size_t)(m0 + t) * D + k0 + seg * 4);
        }
#pragma unroll
        for (int p = 0; p < 6; p++) {
            int c = tid + p * 256;
            int n = c >> 3, seg = c & 7;
            const float* w = (n < 64) ? wq : (n < 128) ? wk : wv;
            cpa16(ws + n * 36 + seg * 4, w + (size_t)(n & 63) * D + k0 + seg * 4);
        }
        CPA_COMMIT();
    };

    float acc[2][12][4];
#pragma unroll
    for (int mt = 0; mt < 2; mt++)
#pragma unroll
        for (int nt = 0; nt < 12; nt++)
#pragma unroll
            for (int e = 0; e < 4; e++) acc[mt][nt][e] = 0.0f;

    load_stage(0, 0);

    for (int it = 0; it < 32; ++it) {
        if (it + 1 < 32) { load_stage((it + 1) & 1, (it + 1) * 32); cpa_wait<1>(); }
        else             { cpa_wait<0>(); }
        __syncthreads();

        const float* xs = ps + (it & 1) * PSTG;
        const float* ws = xs + PXS;
        const float* aB = xs + (wm * 32 + (lane >> 2)) * 36 + (lane & 3);
        const float* bB = ws + (wn * 96 + (lane >> 2)) * 36 + (lane & 3);

#pragma unroll
        for (int s = 0; s < 4; s++) {
            uint32_t a[2][4];
#pragma unroll
            for (int mt = 0; mt < 2; mt++) {
                const float* ap = aB + mt * 16 * 36 + s * 8;
                a[mt][0] = tf32_rna(ap[0]);
                a[mt][1] = tf32_rna(ap[8 * 36]);
                a[mt][2] = tf32_rna(ap[4]);
                a[mt][3] = tf32_rna(ap[8 * 36 + 4]);
            }
#pragma unroll
            for (int nt = 0; nt < 12; nt++) {
                const float* bp = bB + nt * 8 * 36 + s * 8;
                uint32_t b0 = tf32_rna(bp[0]);
                uint32_t b1 = tf32_rna(bp[4]);
                mma8(acc[0][nt], a[0], b0, b1);
                mma8(acc[1][nt], a[1], b0, b1);
            }
        }
        __syncthreads();
    }

    // epilogue: scale (Q only), round to tf32-exact fp32, store
    const float SC = (float)(1.4426950408889634 / 32.0);
#pragma unroll
    for (int mt = 0; mt < 2; mt++) {
#pragma unroll
        for (int nt = 0; nt < 12; nt++) {
            int col = wn * 96 + nt * 8 + 2 * (lane & 3);
            float* outp = (col < 64) ? g_Q : (col < 128) ? g_K : g_V;
            float sc = (col < 64) ? SC : 1.0f;
            int lc  = col & 63;
            int row = m0 + wm * 32 + mt * 16 + (lane >> 2);
            *(float2*)(outp + (size_t)row * DK + lc) =
                make_float2(__uint_as_float(tf32_rna(acc[mt][nt][0] * sc)),
                            __uint_as_float(tf32_rna(acc[mt][nt][1] * sc)));
            *(float2*)(outp + (size_t)(row + 8) * DK + lc) =
                make_float2(__uint_as_float(tf32_rna(acc[mt][nt][2] * sc)),
                            __uint_as_float(tf32_rna(acc[mt][nt][3] * sc)));
        }
    }
}

// ---------------------------------------------------------------------------
// Phase 2: flash attention, 1-term tf32 both GEMMs, zero CVT in inner loops.
// 8 warps x 16 q-rows, 128 kv-tile, causal-paired q-tiles (33 tiles/block).
// ---------------------------------------------------------------------------
constexpr int KSZ  = 128 * 68;
constexpr int VSZ  = 128 * 72;
constexpr int STG  = KSZ + VSZ;
constexpr int POFF = 2 * STG;
constexpr int ATTN_SMEM = (POFF + 128 * 132) * 4;  // 210944 B

__global__ __launch_bounds__(256, 1)
void attn_kernel(float* __restrict__ out)
{
    extern __shared__ float sm[];
    const int b    = blockIdx.y;
    const int pj   = blockIdx.x;
    const int tid  = threadIdx.x;
    const int lane = tid & 31;
    const int warp = tid >> 5;
    const int wb   = warp * 16;
    const int p4   = lane >> 2;
    const int q4   = lane & 3;

    float* Ps = sm + POFF;

    auto load_kv = [&](int kt, int st) {
        float* Ks = sm + st * STG;
        float* Vs = Ks + KSZ;
        const int t0 = kt * 128;
#pragma unroll
        for (int p = 0; p < 8; p++) {
            int c = tid + p * 256;
            int t = c >> 4, seg = c & 15;
            cpa16(Ks + t * 68 + seg * 4, g_K + ((size_t)(b * S + t0 + t)) * 64 + seg * 4);
        }
#pragma unroll
        for (int p = 0; p < 8; p++) {
            int c = tid + p * 256;
            int t = c >> 4, seg = c & 15;
            cpa16(Vs + t * 72 + seg * 4, g_V + ((size_t)(b * S + t0 + t)) * 64 + seg * 4);
        }
        CPA_COMMIT();
    };

    for (int qsel = 0; qsel < 2; qsel++) {
        const int qt = qsel ? (31 - pj) : pj;
        const int q0 = qt * 128;
        const int nt = qt + 1;

        load_kv(0, 0);

        // Q a-frags: values already tf32-exact, reinterpret bits
        uint32_t qa[8][4];
#pragma unroll
        for (int s = 0; s < 8; s++) {
            const float* qp = g_Q + ((size_t)(b * S + q0 + wb + p4)) * 64 + s * 8 + q4;
            qa[s][0] = f2u(qp[0]);
            qa[s][1] = f2u(qp[8 * 64]);
            qa[s][2] = f2u(qp[4]);
            qa[s][3] = f2u(qp[8 * 64 + 4]);
        }

        float of[8][4];
        float m0r = NEG, m1r = NEG, l0 = 0.0f, l1 = 0.0f;
#pragma unroll
        for (int j = 0; j < 8; j++)
#pragma unroll
            for (int e = 0; e < 4; e++) of[j][e] = 0.0f;

        for (int it = 0; it < nt; ++it) {
            const int st = it & 1;
            if (it + 1 < nt) { load_kv(it + 1, st ^ 1); cpa_wait<1>(); }
            else             { cpa_wait<0>(); }
            __syncthreads();

            const float* Ks = sm + st * STG;
            const float* Vs = Ks + KSZ;

            // ---- S = Q K^T  (pure LDS + HMMA) ----
            float sf[16][4];
#pragma unroll
            for (int j = 0; j < 16; j++)
#pragma unroll
                for (int e = 0; e < 4; e++) sf[j][e] = 0.0f;

            const float* kB = Ks + p4 * 68 + q4;
#pragma unroll 4
            for (int j = 0; j < 16; j++) {
                const float* kp = kB + j * 8 * 68;
#pragma unroll
                for (int s = 0; s < 8; s++) {
                    mma8(sf[j], qa[s], f2u(kp[s * 8]), f2u(kp[s * 8 + 4]));
                }
            }

            // ---- causal mask on diagonal tile ----
            if (it == qt) {
                int r0 = wb + p4;
#pragma unroll
                for (int j = 0; j < 16; j++) {
                    int c0 = j * 8 + 2 * q4;
                    if (c0     > r0)     sf[j][0] = NEG;
                    if (c0 + 1 > r0)     sf[j][1] = NEG;
                    if (c0     > r0 + 8) sf[j][2] = NEG;
                    if (c0 + 1 > r0 + 8) sf[j][3] = NEG;
                }
            }

            // ---- online softmax (base 2); P rounded once at store ----
            float mx0 = NEG, mx1 = NEG;
#pragma unroll
            for (int j = 0; j < 16; j++) {
                mx0 = fmaxf(mx0, fmaxf(sf[j][0], sf[j][1]));
                mx1 = fmaxf(mx1, fmaxf(sf[j][2], sf[j][3]));
            }
            mx0 = fmaxf(mx0, __shfl_xor_sync(0xffffffffu, mx0, 1));
            mx0 = fmaxf(mx0, __shfl_xor_sync(0xffffffffu, mx0, 2));
            mx1 = fmaxf(mx1, __shfl_xor_sync(0xffffffffu, mx1, 1));
            mx1 = fmaxf(mx1, __shfl_xor_sync(0xffffffffu, mx1, 2));
            float mn0 = fmaxf(m0r, mx0), mn1 = fmaxf(m1r, mx1);
            float al0 = ex2f(m0r - mn0), al1 = ex2f(m1r - mn1);
            m0r = mn0; m1r = mn1;

            float rs0 = 0.0f, rs1 = 0.0f;
            float* pw = Ps + (wb + p4) * 132 + 2 * q4;
#pragma unroll
            for (int j = 0; j < 16; j++) {
                float p00 = __uint_as_float(tf32_rna(ex2f(sf[j][0] - mn0)));
                float p01 = __uint_as_float(tf32_rna(ex2f(sf[j][1] - mn0)));
                float p10 = __uint_as_float(tf32_rna(ex2f(sf[j][2] - mn1)));
                float p11 = __uint_as_float(tf32_rna(ex2f(sf[j][3] - mn1)));
                rs0 += p00 + p01;
                rs1 += p10 + p11;
                *(float2*)(pw + j * 8)           = make_float2(p00, p01);
                *(float2*)(pw + 8 * 132 + j * 8) = make_float2(p10, p11);
            }
            rs0 += __shfl_xor_sync(0xffffffffu, rs0, 1);
            rs0 += __shfl_xor_sync(0xffffffffu, rs0, 2);
            rs1 += __shfl_xor_sync(0xffffffffu, rs1, 1);
            rs1 += __shfl_xor_sync(0xffffffffu, rs1, 2);
            l0 = l0 * al0 + rs0;
            l1 = l1 * al1 + rs1;
#pragma unroll
            for (int j = 0; j < 8; j++) {
                of[j][0] *= al0; of[j][1] *= al0;
                of[j][2] *= al1; of[j][3] *= al1;
            }
            __syncwarp();   // P rows wb..wb+15 are warp-private

            // ---- O += P V  (pure LDS + HMMA, 1 term) ----
            const float* pA = Ps + (wb + p4) * 132 + q4;
            const float* vB = Vs + q4 * 72 + p4;
#pragma unroll 4
            for (int s2 = 0; s2 < 16; s2++) {
                uint32_t pa[4];
                pa[0] = f2u(pA[s2 * 8]);
                pa[1] = f2u(pA[8 * 132 + s2 * 8]);
                pa[2] = f2u(pA[s2 * 8 + 4]);
                pa[3] = f2u(pA[8 * 132 + s2 * 8 + 4]);
                const float* vp = vB + s2 * 8 * 72;
#pragma unroll
                for (int j2 = 0; j2 < 8; j2++) {
                    mma8(of[j2], pa, f2u(vp[j2 * 8]), f2u(vp[4 * 72 + j2 * 8]));
                }
            }
            __syncthreads();
        }

        // ---- epilogue ----
        float inv0 = 1.0f / l0, inv1 = 1.0f / l1;
        float* orow0 = out + ((size_t)(b * S + q0 + wb + p4)) * 64 + 2 * q4;
        float* orow1 = orow0 + 8 * 64;
#pragma unroll
        for (int j2 = 0; j2 < 8; j2++) {
            *(float2*)(orow0 + j2 * 8) = make_float2(of[j2][0] * inv0, of[j2][1] * inv0);
            *(float2*)(orow1 + j2 * 8) = make_float2(of[j2][2] * inv1, of[j2][3] * inv1);
        }
    }
}

// ---------------------------------------------------------------------------
extern "C" void kernel_launch(void* const* d_in, const int* in_sizes, int n_in,
                              void* d_out, int out_size)
{
    const float* x  = (const float*)d_in[0];
    const float* wq = (const float*)d_in[1];
    const float* wk = (const float*)d_in[2];
    const float* wv = (const float*)d_in[3];
    float* out = (float*)d_out;

    cudaFuncSetAttribute(proj_kernel,
                         cudaFuncAttributeMaxDynamicSharedMemorySize, PROJ_SMEM);
    cudaFuncSetAttribute(attn_kernel,
                         cudaFuncAttributeMaxDynamicSharedMemorySize, ATTN_SMEM);

    proj_kernel<<<M / 128, 256, PROJ_SMEM>>>(x, wq, wk, wv);
    attn_kernel<<<dim3(16, B), 256, ATTN_SMEM>>>(out);
}